// round 10
// baseline (speedup 1.0000x reference)
#include <cuda_runtime.h>
#include <cuda_fp16.h>
#include <cstdint>

#define SEQ   256
#define NB    64
#define INP   1024
#define HID   1024
#define SBH   (SEQ*NB*HID)
#define NCTA  128
#define GST   33          // gsm row stride (floats)
#define GSZ   (64*GST)    // per-region gate area
#define WTILE 16384       // words per W tile per CTA (32 rows x 1024 k, fp16x2)

// ---- device scratch ----
__device__ uint32_t g_xv[(size_t)SEQ*NB*HID/2];  // x*mask_x, fp16x2, A-frag layout per step
__device__ uint32_t g_hm[2][NB*HID/2];           // masked h, fp16x2, A-frag layout
__device__ uint32_t g_wt[(size_t)2*NCTA*WTILE];  // [0]=W_hh tiles, [1]=W_ih tiles (B-frag)
__device__ __half   g_xgh[(size_t)SEQ*NB*HID*4]; // xg, fp16, [t][b][u][g]
__device__ int      g_bar[SEQ];                  // grid barrier counters

__device__ __forceinline__ void mma16h(float* d, const uint32_t* a, const uint32_t* b) {
    asm volatile(
        "mma.sync.aligned.m16n8k16.row.col.f32.f16.f16.f32 "
        "{%0,%1,%2,%3},{%4,%5,%6,%7},{%8,%9},{%0,%1,%2,%3};\n"
        : "+f"(d[0]), "+f"(d[1]), "+f"(d[2]), "+f"(d[3])
        : "r"(a[0]), "r"(a[1]), "r"(a[2]), "r"(a[3]), "r"(b[0]), "r"(b[1]));
}
__device__ __forceinline__ float sigf(float x)  { return 1.f/(1.f+__expf(-x)); }
__device__ __forceinline__ float tanh_f(float x){ return 2.f/(1.f+__expf(-2.f*x)) - 1.f; }
__device__ __forceinline__ void bar_red_release(int* p) {
    asm volatile("red.release.gpu.global.add.s32 [%0], 1;" :: "l"(p) : "memory");
}
__device__ __forceinline__ int bar_ld_acquire(int* p) {
    int v;
    asm volatile("ld.acquire.gpu.global.b32 %0, [%1];" : "=r"(v) : "l"(p) : "memory");
    return v;
}
__device__ __forceinline__ uint32_t packh2(float lo, float hi) {
    __half2 h = __floats2half2_rn(lo, hi);   // lo -> low 16 bits (even k)
    return *reinterpret_cast<uint32_t*>(&h);
}
// fp16 A-frag layout: word address for (batch b, k-pair pk); pk = k/2  (proven)
__device__ __forceinline__ int hp_addr(int b, int pk) {
    int mt = b >> 4, rb = b & 15;
    int c  = pk >> 3, pkl = pk & 7;
    int lane = (rb & 7)*4 + (pkl & 3);
    int e    = (pkl >> 2)*2 + (rb >> 3);
    return (mt*64 + c)*128 + lane*4 + e;
}

// ---- x*mask_x -> fp16x2 A-frag layout, per step (proven) ----
__global__ void k_xprep(const float* __restrict__ x, const float* __restrict__ mx) {
    int i = blockIdx.x*256 + threadIdx.x;
    int t = i >> 15;
    int d = i & 32767;
    int b = d >> 9, pk = d & 511;
    int u0 = pk*2;
    const float* xs = x  + ((size_t)t*NB + b)*INP + u0;
    const float* ms = mx + (size_t)b*INP + u0;
    g_xv[(size_t)t*32768 + hp_addr(b, pk)] = packh2(xs[0]*ms[0], xs[1]*ms[1]);
}

// ---- init: hm0 = fp16x2(h0*mask_h) in frag layout; zero barriers (proven) ----
__global__ void k_setup(const float* __restrict__ h0, const float* __restrict__ mh) {
    int i = blockIdx.x*256 + threadIdx.x;
    int b = i >> 9, pk = i & 511;
    int u0 = pk*2;
    int s = b*HID + u0;
    g_hm[0][hp_addr(b, pk)] = packh2(h0[s]*mh[s], h0[s+1]*mh[s+1]);
    if (blockIdx.x == 0) g_bar[threadIdx.x] = 0;
}

// ---- W prep: per-CTA fp16x2 tiles in B-fragment layout (proven) ----
__global__ void k_wprep(const float* __restrict__ W, int which) {
    int gi = blockIdx.x*256 + threadIdx.x;
    int cb = gi >> 14;
    int d  = gi & 16383;
    int blk = d >> 7;
    int lane_e = d & 127;
    int chunk = blk >> 1, ntp = blk & 1;
    int lane = lane_e >> 2, e = lane_e & 3;
    int lq = lane >> 2, q4 = lane & 3;
    int nt = ntp*2 + (e >> 1);
    int pk_off = q4 + (e & 1)*4;
    int n = nt*8 + lq;
    int g = n >> 3, j = n & 7;
    const float* src = W + ((size_t)(g*HID + cb*8 + j))*HID + (chunk*8 + pk_off)*2;
    g_wt[(size_t)which*NCTA*WTILE + gi] = packh2(src[0], src[1]);
}

// mma micro-step for the xg GEMM: 4 m-tiles x 8 n-tiles
#define XGMMA(AV, BV) do {                                                     \
    _Pragma("unroll")                                                          \
    for (int mt = 0; mt < 4; mt++) {                                           \
        uint32_t af[4] = {(AV)[mt].x, (AV)[mt].y, (AV)[mt].z, (AV)[mt].w};     \
        uint32_t bf0[2] = {(BV)[0].x, (BV)[0].y};                              \
        uint32_t bf1[2] = {(BV)[0].z, (BV)[0].w};                              \
        uint32_t bf2[2] = {(BV)[1].x, (BV)[1].y};                              \
        uint32_t bf3[2] = {(BV)[1].z, (BV)[1].w};                              \
        uint32_t bf4[2] = {(BV)[2].x, (BV)[2].y};                              \
        uint32_t bf5[2] = {(BV)[2].z, (BV)[2].w};                              \
        uint32_t bf6[2] = {(BV)[3].x, (BV)[3].y};                              \
        uint32_t bf7[2] = {(BV)[3].z, (BV)[3].w};                              \
        mma16h(acc[mt][0], af, bf0); mma16h(acc[mt][1], af, bf1);              \
        mma16h(acc[mt][2], af, bf2); mma16h(acc[mt][3], af, bf3);              \
        mma16h(acc[mt][4], af, bf4); mma16h(acc[mt][5], af, bf5);              \
        mma16h(acc[mt][6], af, bf6); mma16h(acc[mt][7], af, bf7);              \
    }                                                                          \
} while (0)

// ---- xg GEMM: xg[t] = W_ih * (x_t*mask_x); CTA = (2 steps) x (256 N cols) ----
// A-frags direct from g_xv (proven layout); B-frags direct from g_wt W_ih tiles.
__global__ void __launch_bounds__(256, 1) k_xgemm() {
    const int tid  = threadIdx.x;
    const int lane = tid & 31;
    const int w    = tid >> 5;
    const int t    = blockIdx.y*2 + (w & 1);   // step handled by this warp
    const int nq   = w >> 1;                   // 0..3
    const int cbb  = blockIdx.x*8 + nq*2;      // first of 2 cb tiles (32 cols each)
    const int lq   = lane >> 2, q4 = lane & 3;

    const uint4* ap  = reinterpret_cast<const uint4*>(g_xv) + (size_t)t*8192 + lane;
    const uint4* bt0 = reinterpret_cast<const uint4*>(g_wt + ((size_t)NCTA + cbb)*WTILE) + lane;
    const uint4* bt1 = reinterpret_cast<const uint4*>(g_wt + ((size_t)NCTA + cbb + 1)*WTILE) + lane;

    float acc[4][8][4];
    #pragma unroll
    for (int mt = 0; mt < 4; mt++)
        #pragma unroll
        for (int nt = 0; nt < 8; nt++)
            #pragma unroll
            for (int e = 0; e < 4; e++) acc[mt][nt][e] = 0.f;

    uint4 ab[2][4], bb[2][4];
    #pragma unroll
    for (int s = 0; s < 2; s++) {
        #pragma unroll
        for (int mt = 0; mt < 4; mt++) ab[s][mt] = __ldcg(ap + mt*2048 + s*32);
        bb[s][0] = __ldcg(bt0 + s*64);  bb[s][1] = __ldcg(bt0 + s*64 + 32);
        bb[s][2] = __ldcg(bt1 + s*64);  bb[s][3] = __ldcg(bt1 + s*64 + 32);
    }

    #pragma unroll 1
    for (int c2 = 0; c2 < 32; ++c2) {
        const int c0 = c2*2;
        // even chunk
        {
            uint4 A[4] = {ab[0][0], ab[0][1], ab[0][2], ab[0][3]};
            uint4 B[4] = {bb[0][0], bb[0][1], bb[0][2], bb[0][3]};
            if (c0 + 2 < 64) {
                #pragma unroll
                for (int mt = 0; mt < 4; mt++) ab[0][mt] = __ldcg(ap + mt*2048 + (c0+2)*32);
                bb[0][0] = __ldcg(bt0 + (c0+2)*64);  bb[0][1] = __ldcg(bt0 + (c0+2)*64 + 32);
                bb[0][2] = __ldcg(bt1 + (c0+2)*64);  bb[0][3] = __ldcg(bt1 + (c0+2)*64 + 32);
            }
            XGMMA(A, B);
        }
        // odd chunk
        {
            uint4 A[4] = {ab[1][0], ab[1][1], ab[1][2], ab[1][3]};
            uint4 B[4] = {bb[1][0], bb[1][1], bb[1][2], bb[1][3]};
            if (c0 + 3 < 64) {
                #pragma unroll
                for (int mt = 0; mt < 4; mt++) ab[1][mt] = __ldcg(ap + mt*2048 + (c0+3)*32);
                bb[1][0] = __ldcg(bt0 + (c0+3)*64);  bb[1][1] = __ldcg(bt0 + (c0+3)*64 + 32);
                bb[1][2] = __ldcg(bt1 + (c0+3)*64);  bb[1][3] = __ldcg(bt1 + (c0+3)*64 + 32);
            }
            XGMMA(A, B);
        }
    }

    // epilogue: write fp16 xg[t][b][u][g]
    #pragma unroll
    for (int mt = 0; mt < 4; mt++) {
        #pragma unroll
        for (int nt = 0; nt < 8; nt++) {
            const int cbx  = cbb + (nt >> 2);
            const int cidx = (nt & 3)*8 + q4*2;       // col within 32-tile (even)
            const int g    = cidx >> 3;
            const int j    = cidx & 7;                // even; pair is j, j+1
            const int u    = cbx*8 + j;
            const int b    = mt*16 + lq;
            size_t base0 = (((size_t)t*NB + b)*HID + u)*4 + g;
            g_xgh[base0]     = __float2half(acc[mt][nt][0]);   // (b,   u,   g)
            g_xgh[base0 + 4] = __float2half(acc[mt][nt][1]);   // (b,   u+1, g)
            size_t base1 = base0 + (size_t)8*HID*4;
            g_xgh[base1]     = __float2half(acc[mt][nt][2]);   // (b+8, u,   g)
            g_xgh[base1 + 4] = __float2half(acc[mt][nt][3]);   // (b+8, u+1, g)
        }
    }
}

// per-warp h-GEMM over K=256 (proven R8 MMA_BLOCK)
#define MMA_BLOCK(ABASE, W4) do {                                              \
    const uint4* ap0 = (ABASE) + half*2*2048 + kq*512 + lane;                  \
    const uint4* ap1 = ap0 + 2048;                                             \
    uint4 afr[8][2];                                                           \
    _Pragma("unroll")                                                          \
    for (int s = 0; s < 8; s++) {                                              \
        afr[s][0] = __ldcg(ap0 + s*32);                                        \
        afr[s][1] = __ldcg(ap1 + s*32);                                        \
    }                                                                          \
    _Pragma("unroll")                                                          \
    for (int g8 = 0; g8 < 2; g8++) {                                           \
        _Pragma("unroll")                                                      \
        for (int s = 0; s < 8; s++) {                                          \
            const int cq = g8*8 + s;                                           \
            uint4 A0 = afr[s][0], A1 = afr[s][1];                              \
            if (g8 == 0) {                                                     \
                afr[s][0] = __ldcg(ap0 + (cq+8)*32);                           \
                afr[s][1] = __ldcg(ap1 + (cq+8)*32);                           \
            }                                                                  \
            const int bidx = (kq*16 + cq)*64 + lane;                           \
            uint4 b01 = (W4)[bidx];                                            \
            uint4 b23 = (W4)[bidx + 32];                                       \
            uint32_t af0[4] = {A0.x, A0.y, A0.z, A0.w};                        \
            uint32_t af1[4] = {A1.x, A1.y, A1.z, A1.w};                        \
            uint32_t bf0[2] = {b01.x, b01.y};                                  \
            uint32_t bf1[2] = {b01.z, b01.w};                                  \
            uint32_t bf2[2] = {b23.x, b23.y};                                  \
            uint32_t bf3[2] = {b23.z, b23.w};                                  \
            mma16h(acc[0][0], af0, bf0); mma16h(acc[1][0], af1, bf0);          \
            mma16h(acc[0][1], af0, bf1); mma16h(acc[1][1], af1, bf1);          \
            mma16h(acc[0][2], af0, bf2); mma16h(acc[1][2], af1, bf2);          \
            mma16h(acc[0][3], af0, bf3); mma16h(acc[1][3], af1, bf3);          \
        }                                                                      \
    }                                                                          \
} while (0)

// ---- persistent LSTM recurrence: h-GEMM only, xg precomputed ----
__global__ void __launch_bounds__(256, 1) k_rnn(const float* __restrict__ c0,
                                                const float* __restrict__ mh,
                                                const float* __restrict__ b_ih,
                                                const float* __restrict__ b_hh,
                                                float* __restrict__ out) {
    extern __shared__ uint32_t sm[];
    uint32_t* sWh = sm;                    // W_hh tile, 16384 words
    float*    gsm = (float*)(sm + WTILE);

    const int cb   = blockIdx.x;
    const int tid  = threadIdx.x;
    const int lane = tid & 31;
    const int w    = tid >> 5;
    const int half = w & 1;                // batch half
    const int kq   = w >> 1;               // k quarter (K=256 per warp)

    {
        const uint4* s0 = reinterpret_cast<const uint4*>(g_wt + (size_t)cb*WTILE);
        uint4* d0 = reinterpret_cast<uint4*>(sWh);
        #pragma unroll
        for (int i = 0; i < 16; i++) d0[tid + i*256] = __ldcg(s0 + tid + i*256);
    }

    const int pb = tid >> 2;
    const int p  = tid & 3;
    const int u0 = cb*8 + 2*p;
    const int gbase = pb*HID + u0;

    float2 c_r = *reinterpret_cast<const float2*>(c0 + gbase);
    float2 mh2 = *reinterpret_cast<const float2*>(mh + gbase);
    const int hwaddr = hp_addr(pb, cb*4 + p);

    float bs[2][4];
    #pragma unroll
    for (int i = 0; i < 2; i++)
        #pragma unroll
        for (int g = 0; g < 4; g++)
            bs[i][g] = b_ih[g*HID + u0 + i] + b_hh[g*HID + u0 + i];
    __syncthreads();

    const uint4* wh4 = reinterpret_cast<const uint4*>(sWh);
    const uint4* xg4 = reinterpret_cast<const uint4*>(g_xgh);
    const int xgoff = (pb << 9) + cb*4 + p;   // per-thread offset within a step's xg block

    // xg prefetch for t=0
    float xr[2][4];
    {
        uint4 q = __ldg(xg4 + xgoff);
        const __half* hq = reinterpret_cast<const __half*>(&q);
        #pragma unroll
        for (int g = 0; g < 4; g++) {
            xr[0][g] = __half2float(hq[g]);
            xr[1][g] = __half2float(hq[4 + g]);
        }
    }

    for (int t = 0; t < SEQ; ++t) {
        // wait until all CTAs have published h[t]
        if (t > 0) {
            if (tid == 0) {
                while (bar_ld_acquire(&g_bar[t-1]) < NCTA) { }
            }
            __syncthreads();
        }

        float acc[2][4][4];
        #pragma unroll
        for (int mt = 0; mt < 2; mt++)
            #pragma unroll
            for (int nt = 0; nt < 4; nt++)
                #pragma unroll
                for (int e = 0; e < 4; e++) acc[mt][nt][e] = 0.f;

        {
            const uint4* hb = reinterpret_cast<const uint4*>(g_hm[t & 1]);
            MMA_BLOCK(hb, wh4);
        }

        // stage split-K partial gates (proven)
        {
            const int lq = lane >> 2, q4 = lane & 3;
            float* gp = gsm + kq*GSZ;
            #pragma unroll
            for (int mt = 0; mt < 2; mt++) {
                const int r0 = half*32 + mt*16 + lq;
                #pragma unroll
                for (int nt = 0; nt < 4; nt++) {
                    const int c = nt*8 + q4*2;
                    gp[r0*GST + c]       = acc[mt][nt][0];
                    gp[r0*GST + c + 1]   = acc[mt][nt][1];
                    gp[(r0+8)*GST + c]   = acc[mt][nt][2];
                    gp[(r0+8)*GST + c+1] = acc[mt][nt][3];
                }
            }
        }
        __syncthreads();

        // fused LSTM cell (proven)
        uint32_t* hmn = g_hm[(t + 1) & 1];
        float hnv[2], cnv[2];
        #pragma unroll
        for (int i = 0; i < 2; i++) {
            const int j = 2*p + i;
            float gt[4];
            #pragma unroll
            for (int g = 0; g < 4; g++) {
                const int c = g*8 + j;
                gt[g] = gsm[0*GSZ + pb*GST + c] + gsm[1*GSZ + pb*GST + c]
                      + gsm[2*GSZ + pb*GST + c] + gsm[3*GSZ + pb*GST + c]
                      + xr[i][g] + bs[i][g];
            }
            float ig = sigf(gt[0]);
            float fg = sigf(gt[1]);
            float gv = tanh_f(gt[2]);
            float og = sigf(gt[3]);
            float cp = (i == 0) ? c_r.x : c_r.y;
            float cn = fg*cp + ig*gv;
            cnv[i] = cn;
            hnv[i] = og*tanh_f(cn);
        }
        c_r.x = cnv[0]; c_r.y = cnv[1];

        *reinterpret_cast<float2*>(out + (size_t)t*(NB*HID) + gbase)
            = make_float2(hnv[0], hnv[1]);
        hmn[hwaddr] = packh2(hnv[0]*mh2.x, hnv[1]*mh2.y);
        if (t == SEQ - 1) {
            *reinterpret_cast<float2*>(out + SBH + gbase)          = make_float2(hnv[0], hnv[1]);
            *reinterpret_cast<float2*>(out + SBH + NB*HID + gbase) = make_float2(cnv[0], cnv[1]);
        }

        if (t < SEQ - 1) {
            __syncthreads();                            // all hmn writes done CTA-wide
            if (tid == 0) bar_red_release(&g_bar[t]);   // arrive (release)

            // prefetch next step's xg in the shadow of other CTAs arriving
            {
                uint4 q = __ldg(xg4 + (size_t)(t+1)*(NB*512) + xgoff);
                const __half* hq = reinterpret_cast<const __half*>(&q);
                #pragma unroll
                for (int g = 0; g < 4; g++) {
                    xr[0][g] = __half2float(hq[g]);
                    xr[1][g] = __half2float(hq[4 + g]);
                }
            }
        }
    }
}

extern "C" void kernel_launch(void* const* d_in, const int* in_sizes, int n_in,
                              void* d_out, int out_size) {
    const float* x      = (const float*)d_in[0];
    const float* h0     = (const float*)d_in[1];
    const float* c0     = (const float*)d_in[2];
    const float* mask_x = (const float*)d_in[3];
    const float* mask_h = (const float*)d_in[4];
    const float* W_ih   = (const float*)d_in[5];
    const float* W_hh   = (const float*)d_in[6];
    const float* b_ih   = (const float*)d_in[7];
    const float* b_hh   = (const float*)d_in[8];
    float* out = (float*)d_out;

    const int smem_rnn = (WTILE + 4*GSZ) * 4;   // 65536 + 33792 = 99,328 B
    cudaFuncSetAttribute(k_rnn, cudaFuncAttributeMaxDynamicSharedMemorySize, smem_rnn);

    k_xprep<<<(SEQ*NB*HID/2)/256, 256>>>(x, mask_x);
    k_setup<<<(NB*HID/2)/256, 256>>>(h0, mask_h);
    k_wprep<<<(NCTA*WTILE)/256, 256>>>(W_hh, 0);
    k_wprep<<<(NCTA*WTILE)/256, 256>>>(W_ih, 1);
    k_xgemm<<<dim3(16, 128), 256>>>();
    k_rnn<<<NCTA, 256, smem_rnn>>>(c0, mask_h, b_ih, b_hh, out);
    (void)in_sizes; (void)n_in; (void)out_size;
}

// round 11
// speedup vs baseline: 1.0595x; 1.0595x over previous
#include <cuda_runtime.h>
#include <cuda_fp16.h>
#include <cstdint>

#define SEQ   256
#define NB    64
#define INP   1024
#define HID   1024
#define SBH   (SEQ*NB*HID)
#define NCTA  128
#define GST   33          // gsm row stride (floats)
#define GSZ   (64*GST)    // per-region gate area
#define WTILE 16384       // words per W tile per CTA (32 rows x 1024 k, fp16x2)
#define XST   3072        // xgemm stage words: A 8 blocks + B 16 blocks, 128 words each
#define XNST  8           // xgemm pipeline stages

// ---- device scratch ----
__device__ uint32_t g_xv[(size_t)SEQ*NB*HID/2];  // x*mask_x, fp16x2, A-frag layout per step
__device__ uint32_t g_hm[2][NB*HID/2];           // masked h, fp16x2, A-frag layout
__device__ uint32_t g_wt[(size_t)2*NCTA*WTILE];  // [0]=W_hh tiles, [1]=W_ih tiles (B-frag)
__device__ __half   g_xgh[(size_t)SEQ*NB*HID*4]; // xg, fp16, [t][b][u][g]
__device__ int      g_bar[SEQ];                  // grid barrier counters

__device__ __forceinline__ void mma16h(float* d, const uint32_t* a, const uint32_t* b) {
    asm volatile(
        "mma.sync.aligned.m16n8k16.row.col.f32.f16.f16.f32 "
        "{%0,%1,%2,%3},{%4,%5,%6,%7},{%8,%9},{%0,%1,%2,%3};\n"
        : "+f"(d[0]), "+f"(d[1]), "+f"(d[2]), "+f"(d[3])
        : "r"(a[0]), "r"(a[1]), "r"(a[2]), "r"(a[3]), "r"(b[0]), "r"(b[1]));
}
__device__ __forceinline__ float sigf(float x)  { return 1.f/(1.f+__expf(-x)); }
__device__ __forceinline__ float tanh_f(float x){ return 2.f/(1.f+__expf(-2.f*x)) - 1.f; }
__device__ __forceinline__ void bar_red_release(int* p) {
    asm volatile("red.release.gpu.global.add.s32 [%0], 1;" :: "l"(p) : "memory");
}
__device__ __forceinline__ int bar_ld_acquire(int* p) {
    int v;
    asm volatile("ld.acquire.gpu.global.b32 %0, [%1];" : "=r"(v) : "l"(p) : "memory");
    return v;
}
__device__ __forceinline__ void cpa16(uint32_t d, const void* s) {
    asm volatile("cp.async.cg.shared.global [%0], [%1], 16;\n" :: "r"(d), "l"(s));
}
__device__ __forceinline__ uint32_t packh2(float lo, float hi) {
    __half2 h = __floats2half2_rn(lo, hi);   // lo -> low 16 bits (even k)
    return *reinterpret_cast<uint32_t*>(&h);
}
// fp16 A-frag layout: word address for (batch b, k-pair pk); pk = k/2  (proven)
__device__ __forceinline__ int hp_addr(int b, int pk) {
    int mt = b >> 4, rb = b & 15;
    int c  = pk >> 3, pkl = pk & 7;
    int lane = (rb & 7)*4 + (pkl & 3);
    int e    = (pkl >> 2)*2 + (rb >> 3);
    return (mt*64 + c)*128 + lane*4 + e;
}

// ---- x*mask_x -> fp16x2 A-frag layout, per step (proven) ----
__global__ void k_xprep(const float* __restrict__ x, const float* __restrict__ mx) {
    int i = blockIdx.x*256 + threadIdx.x;
    int t = i >> 15;
    int d = i & 32767;
    int b = d >> 9, pk = d & 511;
    int u0 = pk*2;
    const float* xs = x  + ((size_t)t*NB + b)*INP + u0;
    const float* ms = mx + (size_t)b*INP + u0;
    g_xv[(size_t)t*32768 + hp_addr(b, pk)] = packh2(xs[0]*ms[0], xs[1]*ms[1]);
}

// ---- init: hm0 = fp16x2(h0*mask_h) in frag layout; zero barriers (proven) ----
__global__ void k_setup(const float* __restrict__ h0, const float* __restrict__ mh) {
    int i = blockIdx.x*256 + threadIdx.x;
    int b = i >> 9, pk = i & 511;
    int u0 = pk*2;
    int s = b*HID + u0;
    g_hm[0][hp_addr(b, pk)] = packh2(h0[s]*mh[s], h0[s+1]*mh[s+1]);
    if (blockIdx.x == 0) g_bar[threadIdx.x] = 0;
}

// ---- W prep: per-CTA fp16x2 tiles in B-fragment layout (proven) ----
__global__ void k_wprep(const float* __restrict__ W, int which) {
    int gi = blockIdx.x*256 + threadIdx.x;
    int cb = gi >> 14;
    int d  = gi & 16383;
    int blk = d >> 7;
    int lane_e = d & 127;
    int chunk = blk >> 1, ntp = blk & 1;
    int lane = lane_e >> 2, e = lane_e & 3;
    int lq = lane >> 2, q4 = lane & 3;
    int nt = ntp*2 + (e >> 1);
    int pk_off = q4 + (e & 1)*4;
    int n = nt*8 + lq;
    int g = n >> 3, j = n & 7;
    const float* src = W + ((size_t)(g*HID + cb*8 + j))*HID + (chunk*8 + pk_off)*2;
    g_wt[(size_t)which*NCTA*WTILE + gi] = packh2(src[0], src[1]);
}

// mma micro-step for the xg GEMM: 4 m-tiles x 8 n-tiles (proven R10)
#define XGMMA(AV, BV) do {                                                     \
    _Pragma("unroll")                                                          \
    for (int mt = 0; mt < 4; mt++) {                                           \
        uint32_t af[4] = {(AV)[mt].x, (AV)[mt].y, (AV)[mt].z, (AV)[mt].w};     \
        uint32_t bf0[2] = {(BV)[0].x, (BV)[0].y};                              \
        uint32_t bf1[2] = {(BV)[0].z, (BV)[0].w};                              \
        uint32_t bf2[2] = {(BV)[1].x, (BV)[1].y};                              \
        uint32_t bf3[2] = {(BV)[1].z, (BV)[1].w};                              \
        uint32_t bf4[2] = {(BV)[2].x, (BV)[2].y};                              \
        uint32_t bf5[2] = {(BV)[2].z, (BV)[2].w};                              \
        uint32_t bf6[2] = {(BV)[3].x, (BV)[3].y};                              \
        uint32_t bf7[2] = {(BV)[3].z, (BV)[3].w};                              \
        mma16h(acc[mt][0], af, bf0); mma16h(acc[mt][1], af, bf1);              \
        mma16h(acc[mt][2], af, bf2); mma16h(acc[mt][3], af, bf3);              \
        mma16h(acc[mt][4], af, bf4); mma16h(acc[mt][5], af, bf5);              \
        mma16h(acc[mt][6], af, bf6); mma16h(acc[mt][7], af, bf7);              \
    }                                                                          \
} while (0)

// ---- xg GEMM v3: CTA tile M=128 (2 steps) x N=256 (8 cb), 8-stage cp.async ring.
// A/B gmem data already in proven fragment layouts; SMEM stages whole 128-word
// fragment blocks, consumption indexing identical to the proven R10 path.
__global__ void __launch_bounds__(256, 1) k_xgemm() {
    extern __shared__ uint32_t sx[];           // XNST * XST words
    const int tid  = threadIdx.x;
    const int lane = tid & 31;
    const int w    = tid >> 5;
    const int wy   = w & 1;                    // t-local (0/1)
    const int wx   = w >> 1;                   // 0..3 -> 2 cb tiles each
    const int lq   = lane >> 2, q4 = lane & 3;
    const int t0   = blockIdx.y * 2;
    const int cb0  = blockIdx.x * 8;

    uint32_t sbase = (uint32_t)__cvta_generic_to_shared(sx);

    // stage layout (words): A blocks [tl*4+mt]*128 (8 blocks), then B blocks
    // 1024 + (cb*2+ntp)*128 (16 blocks). 768 uint4 per stage = 3 cpa16/thread.
    auto issue = [&](int st, int c) {
        #pragma unroll
        for (int j = 0; j < 3; j++) {
            int seg = tid + j*256;             // 0..767
            int blk = seg >> 5, l32 = seg & 31;
            const uint32_t* src;
            if (blk < 8) {
                int tl = blk >> 2, mt = blk & 3;
                src = g_xv + (size_t)(t0 + tl)*32768 + (mt*64 + c)*128 + l32*4;
            } else {
                int idx = blk - 8;
                int cbx = idx >> 1, ntp = idx & 1;
                src = g_wt + ((size_t)(NCTA + cb0 + cbx))*WTILE + (c*2 + ntp)*128 + l32*4;
            }
            cpa16(sbase + (uint32_t)(st*XST + blk*128 + l32*4)*4, src);
        }
    };

    #pragma unroll
    for (int s = 0; s < XNST - 1; s++) {
        issue(s, s);
        asm volatile("cp.async.commit_group;\n");
    }

    float acc[4][8][4];
    #pragma unroll
    for (int mt = 0; mt < 4; mt++)
        #pragma unroll
        for (int nt = 0; nt < 8; nt++)
            #pragma unroll
            for (int e = 0; e < 4; e++) acc[mt][nt][e] = 0.f;

    #pragma unroll 1
    for (int c = 0; c < 64; ++c) {
        asm volatile("cp.async.wait_group %0;\n" :: "n"(XNST - 2));
        __syncthreads();
        if (c + XNST - 1 < 64) issue((c + XNST - 1) & (XNST - 1), c + XNST - 1);
        asm volatile("cp.async.commit_group;\n");

        const uint32_t* S = sx + (c & (XNST - 1))*XST;
        uint4 A[4], B[4];
        #pragma unroll
        for (int mt = 0; mt < 4; mt++)
            A[mt] = *reinterpret_cast<const uint4*>(&S[(wy*4 + mt)*128 + lane*4]);
        #pragma unroll
        for (int cbl = 0; cbl < 2; cbl++) {
            const int base = 1024 + (wx*2 + cbl)*2*128;
            B[cbl*2]     = *reinterpret_cast<const uint4*>(&S[base + lane*4]);
            B[cbl*2 + 1] = *reinterpret_cast<const uint4*>(&S[base + 128 + lane*4]);
        }
        XGMMA(A, B);
    }

    // epilogue (proven R10): write fp16 xg[t][b][u][g]
    const int t   = t0 + wy;
    const int cbb = cb0 + wx*2;
    #pragma unroll
    for (int mt = 0; mt < 4; mt++) {
        #pragma unroll
        for (int nt = 0; nt < 8; nt++) {
            const int cbx  = cbb + (nt >> 2);
            const int cidx = (nt & 3)*8 + q4*2;
            const int g    = cidx >> 3;
            const int j    = cidx & 7;
            const int u    = cbx*8 + j;
            const int b    = mt*16 + lq;
            size_t base0 = (((size_t)t*NB + b)*HID + u)*4 + g;
            g_xgh[base0]     = __float2half(acc[mt][nt][0]);
            g_xgh[base0 + 4] = __float2half(acc[mt][nt][1]);
            size_t base1 = base0 + (size_t)8*HID*4;
            g_xgh[base1]     = __float2half(acc[mt][nt][2]);
            g_xgh[base1 + 4] = __float2half(acc[mt][nt][3]);
        }
    }
}

// per-warp h-GEMM over K=256 (proven R8/R10 MMA_BLOCK)
#define MMA_BLOCK(ABASE, W4) do {                                              \
    const uint4* ap0 = (ABASE) + half*2*2048 + kq*512 + lane;                  \
    const uint4* ap1 = ap0 + 2048;                                             \
    uint4 afr[8][2];                                                           \
    _Pragma("unroll")                                                          \
    for (int s = 0; s < 8; s++) {                                              \
        afr[s][0] = __ldcg(ap0 + s*32);                                        \
        afr[s][1] = __ldcg(ap1 + s*32);                                        \
    }                                                                          \
    _Pragma("unroll")                                                          \
    for (int g8 = 0; g8 < 2; g8++) {                                           \
        _Pragma("unroll")                                                      \
        for (int s = 0; s < 8; s++) {                                          \
            const int cq = g8*8 + s;                                           \
            uint4 A0 = afr[s][0], A1 = afr[s][1];                              \
            if (g8 == 0) {                                                     \
                afr[s][0] = __ldcg(ap0 + (cq+8)*32);                           \
                afr[s][1] = __ldcg(ap1 + (cq+8)*32);                           \
            }                                                                  \
            const int bidx = (kq*16 + cq)*64 + lane;                           \
            uint4 b01 = (W4)[bidx];                                            \
            uint4 b23 = (W4)[bidx + 32];                                       \
            uint32_t af0[4] = {A0.x, A0.y, A0.z, A0.w};                        \
            uint32_t af1[4] = {A1.x, A1.y, A1.z, A1.w};                        \
            uint32_t bf0[2] = {b01.x, b01.y};                                  \
            uint32_t bf1[2] = {b01.z, b01.w};                                  \
            uint32_t bf2[2] = {b23.x, b23.y};                                  \
            uint32_t bf3[2] = {b23.z, b23.w};                                  \
            mma16h(acc[0][0], af0, bf0); mma16h(acc[1][0], af1, bf0);          \
            mma16h(acc[0][1], af0, bf1); mma16h(acc[1][1], af1, bf1);          \
            mma16h(acc[0][2], af0, bf2); mma16h(acc[1][2], af1, bf2);          \
            mma16h(acc[0][3], af0, bf3); mma16h(acc[1][3], af1, bf3);          \
        }                                                                      \
    }                                                                          \
} while (0)

// ---- persistent LSTM recurrence: h-GEMM only, xg precomputed (R10 + early release) ----
__global__ void __launch_bounds__(256, 1) k_rnn(const float* __restrict__ c0,
                                                const float* __restrict__ mh,
                                                const float* __restrict__ b_ih,
                                                const float* __restrict__ b_hh,
                                                float* __restrict__ out) {
    extern __shared__ uint32_t sm[];
    uint32_t* sWh = sm;                    // W_hh tile, 16384 words
    float*    gsm = (float*)(sm + WTILE);

    const int cb   = blockIdx.x;
    const int tid  = threadIdx.x;
    const int lane = tid & 31;
    const int w    = tid >> 5;
    const int half = w & 1;                // batch half
    const int kq   = w >> 1;               // k quarter (K=256 per warp)

    {
        const uint4* s0 = reinterpret_cast<const uint4*>(g_wt + (size_t)cb*WTILE);
        uint4* d0 = reinterpret_cast<uint4*>(sWh);
        #pragma unroll
        for (int i = 0; i < 16; i++) d0[tid + i*256] = __ldcg(s0 + tid + i*256);
    }

    const int pb = tid >> 2;
    const int p  = tid & 3;
    const int u0 = cb*8 + 2*p;
    const int gbase = pb*HID + u0;

    float2 c_r = *reinterpret_cast<const float2*>(c0 + gbase);
    float2 mh2 = *reinterpret_cast<const float2*>(mh + gbase);
    const int hwaddr = hp_addr(pb, cb*4 + p);

    float bs[2][4];
    #pragma unroll
    for (int i = 0; i < 2; i++)
        #pragma unroll
        for (int g = 0; g < 4; g++)
            bs[i][g] = b_ih[g*HID + u0 + i] + b_hh[g*HID + u0 + i];
    __syncthreads();

    const uint4* wh4 = reinterpret_cast<const uint4*>(sWh);
    const uint4* xg4 = reinterpret_cast<const uint4*>(g_xgh);
    const int xgoff = (pb << 9) + cb*4 + p;

    // xg prefetch for t=0
    float xr[2][4];
    {
        uint4 q = __ldg(xg4 + xgoff);
        const __half* hq = reinterpret_cast<const __half*>(&q);
        #pragma unroll
        for (int g = 0; g < 4; g++) {
            xr[0][g] = __half2float(hq[g]);
            xr[1][g] = __half2float(hq[4 + g]);
        }
    }

    for (int t = 0; t < SEQ; ++t) {
        // wait until all CTAs have published h[t]
        if (t > 0) {
            if (tid == 0) {
                while (bar_ld_acquire(&g_bar[t-1]) < NCTA) { }
            }
            __syncthreads();
        }

        float acc[2][4][4];
        #pragma unroll
        for (int mt = 0; mt < 2; mt++)
            #pragma unroll
            for (int nt = 0; nt < 4; nt++)
                #pragma unroll
                for (int e = 0; e < 4; e++) acc[mt][nt][e] = 0.f;

        {
            const uint4* hb = reinterpret_cast<const uint4*>(g_hm[t & 1]);
            MMA_BLOCK(hb, wh4);
        }

        // stage split-K partial gates (proven)
        {
            const int lq = lane >> 2, q4 = lane & 3;
            float* gp = gsm + kq*GSZ;
            #pragma unroll
            for (int mt = 0; mt < 2; mt++) {
                const int r0 = half*32 + mt*16 + lq;
                #pragma unroll
                for (int nt = 0; nt < 4; nt++) {
                    const int c = nt*8 + q4*2;
                    gp[r0*GST + c]       = acc[mt][nt][0];
                    gp[r0*GST + c + 1]   = acc[mt][nt][1];
                    gp[(r0+8)*GST + c]   = acc[mt][nt][2];
                    gp[(r0+8)*GST + c+1] = acc[mt][nt][3];
                }
            }
        }
        __syncthreads();

        // fused LSTM cell (proven)
        uint32_t* hmn = g_hm[(t + 1) & 1];
        float hnv[2], cnv[2];
        #pragma unroll
        for (int i = 0; i < 2; i++) {
            const int j = 2*p + i;
            float gt[4];
            #pragma unroll
            for (int g = 0; g < 4; g++) {
                const int c = g*8 + j;
                gt[g] = gsm[0*GSZ + pb*GST + c] + gsm[1*GSZ + pb*GST + c]
                      + gsm[2*GSZ + pb*GST + c] + gsm[3*GSZ + pb*GST + c]
                      + xr[i][g] + bs[i][g];
            }
            float ig = sigf(gt[0]);
            float fg = sigf(gt[1]);
            float gv = tanh_f(gt[2]);
            float og = sigf(gt[3]);
            float cp = (i == 0) ? c_r.x : c_r.y;
            float cn = fg*cp + ig*gv;
            cnv[i] = cn;
            hnv[i] = og*tanh_f(cn);
        }
        c_r.x = cnv[0]; c_r.y = cnv[1];

        // publish h[t+1] FIRST, release, then do private gmem work in the shadow
        hmn[hwaddr] = packh2(hnv[0]*mh2.x, hnv[1]*mh2.y);
        if (t < SEQ - 1) {
            __syncthreads();                            // all hmn writes done CTA-wide
            if (tid == 0) bar_red_release(&g_bar[t]);   // arrive (release)
        }

        *reinterpret_cast<float2*>(out + (size_t)t*(NB*HID) + gbase)
            = make_float2(hnv[0], hnv[1]);
        if (t == SEQ - 1) {
            *reinterpret_cast<float2*>(out + SBH + gbase)          = make_float2(hnv[0], hnv[1]);
            *reinterpret_cast<float2*>(out + SBH + NB*HID + gbase) = make_float2(cnv[0], cnv[1]);
        }

        if (t < SEQ - 1) {
            // prefetch next step's xg in the shadow of other CTAs arriving
            uint4 q = __ldg(xg4 + (size_t)(t+1)*(NB*512) + xgoff);
            const __half* hq = reinterpret_cast<const __half*>(&q);
            #pragma unroll
            for (int g = 0; g < 4; g++) {
                xr[0][g] = __half2float(hq[g]);
                xr[1][g] = __half2float(hq[4 + g]);
            }
        }
    }
}

extern "C" void kernel_launch(void* const* d_in, const int* in_sizes, int n_in,
                              void* d_out, int out_size) {
    const float* x      = (const float*)d_in[0];
    const float* h0     = (const float*)d_in[1];
    const float* c0     = (const float*)d_in[2];
    const float* mask_x = (const float*)d_in[3];
    const float* mask_h = (const float*)d_in[4];
    const float* W_ih   = (const float*)d_in[5];
    const float* W_hh   = (const float*)d_in[6];
    const float* b_ih   = (const float*)d_in[7];
    const float* b_hh   = (const float*)d_in[8];
    float* out = (float*)d_out;

    const int smem_rnn   = (WTILE + 4*GSZ) * 4;     // 99,328 B
    const int smem_xgemm = XNST * XST * 4;          // 98,304 B
    cudaFuncSetAttribute(k_rnn,   cudaFuncAttributeMaxDynamicSharedMemorySize, smem_rnn);
    cudaFuncSetAttribute(k_xgemm, cudaFuncAttributeMaxDynamicSharedMemorySize, smem_xgemm);

    k_xprep<<<(SEQ*NB*HID/2)/256, 256>>>(x, mask_x);
    k_setup<<<(NB*HID/2)/256, 256>>>(h0, mask_h);
    k_wprep<<<(NCTA*WTILE)/256, 256>>>(W_hh, 0);
    k_wprep<<<(NCTA*WTILE)/256, 256>>>(W_ih, 1);
    k_xgemm<<<dim3(16, 128), 256, smem_xgemm>>>();
    k_rnn<<<NCTA, 256, smem_rnn>>>(c0, mask_h, b_ih, b_hh, out);
    (void)in_sizes; (void)n_in; (void)out_size;
}

// round 12
// speedup vs baseline: 1.3588x; 1.2825x over previous
#include <cuda_runtime.h>
#include <cuda_fp16.h>
#include <cstdint>

#define SEQ   256
#define NB    64
#define INP   1024
#define HID   1024
#define SBH   (SEQ*NB*HID)
#define NCTA  128
#define GST   33          // gsm row stride (floats)
#define GSZ   (64*GST)    // per-region gate area
#define WTILE 16384       // words per W tile per CTA (32 rows x 1024 k, fp16x2)

// ---- device scratch ----
__device__ uint32_t g_xv[(size_t)SEQ*NB*HID/2];  // x*mask_x, fp16x2, A-frag layout per step
__device__ uint32_t g_hm[2][NB*HID/2];           // masked h, fp16x2, A-frag layout
__device__ uint32_t g_wt[(size_t)2*NCTA*WTILE];  // [0]=W_hh tiles, [1]=W_ih tiles (B-frag)
__device__ int      g_bar[SEQ];                  // grid barrier counters

__device__ __forceinline__ void mma16h(float* d, const uint32_t* a, const uint32_t* b) {
    asm volatile(
        "mma.sync.aligned.m16n8k16.row.col.f32.f16.f16.f32 "
        "{%0,%1,%2,%3},{%4,%5,%6,%7},{%8,%9},{%0,%1,%2,%3};\n"
        : "+f"(d[0]), "+f"(d[1]), "+f"(d[2]), "+f"(d[3])
        : "r"(a[0]), "r"(a[1]), "r"(a[2]), "r"(a[3]), "r"(b[0]), "r"(b[1]));
}
__device__ __forceinline__ float sigf(float x)  { return 1.f/(1.f+__expf(-x)); }
__device__ __forceinline__ float tanh_f(float x){ return 2.f/(1.f+__expf(-2.f*x)) - 1.f; }
__device__ __forceinline__ void bar_red_release(int* p) {
    asm volatile("red.release.gpu.global.add.s32 [%0], 1;" :: "l"(p) : "memory");
}
__device__ __forceinline__ int bar_ld_acquire(int* p) {
    int v;
    asm volatile("ld.acquire.gpu.global.b32 %0, [%1];" : "=r"(v) : "l"(p) : "memory");
    return v;
}
__device__ __forceinline__ uint32_t packh2(float lo, float hi) {
    __half2 h = __floats2half2_rn(lo, hi);   // lo -> low 16 bits (even k)
    return *reinterpret_cast<uint32_t*>(&h);
}
// fp16 A-frag layout: word address for (batch b, k-pair pk); pk = k/2  (proven)
__device__ __forceinline__ int hp_addr(int b, int pk) {
    int mt = b >> 4, rb = b & 15;
    int c  = pk >> 3, pkl = pk & 7;
    int lane = (rb & 7)*4 + (pkl & 3);
    int e    = (pkl >> 2)*2 + (rb >> 3);
    return (mt*64 + c)*128 + lane*4 + e;
}

// ---- x*mask_x -> fp16x2 A-frag layout, per step (proven) ----
__global__ void k_xprep(const float* __restrict__ x, const float* __restrict__ mx) {
    int i = blockIdx.x*256 + threadIdx.x;
    int t = i >> 15;
    int d = i & 32767;
    int b = d >> 9, pk = d & 511;
    int u0 = pk*2;
    const float* xs = x  + ((size_t)t*NB + b)*INP + u0;
    const float* ms = mx + (size_t)b*INP + u0;
    g_xv[(size_t)t*32768 + hp_addr(b, pk)] = packh2(xs[0]*ms[0], xs[1]*ms[1]);
}

// ---- init: hm0 = fp16x2(h0*mask_h) in frag layout; zero barriers (proven) ----
__global__ void k_setup(const float* __restrict__ h0, const float* __restrict__ mh) {
    int i = blockIdx.x*256 + threadIdx.x;
    int b = i >> 9, pk = i & 511;
    int u0 = pk*2;
    int s = b*HID + u0;
    g_hm[0][hp_addr(b, pk)] = packh2(h0[s]*mh[s], h0[s+1]*mh[s+1]);
    if (blockIdx.x == 0) g_bar[threadIdx.x] = 0;
}

// ---- W prep: per-CTA fp16x2 tiles in B-fragment layout (proven) ----
__global__ void k_wprep(const float* __restrict__ W, int which) {
    int gi = blockIdx.x*256 + threadIdx.x;
    int cb = gi >> 14;
    int d  = gi & 16383;
    int blk = d >> 7;
    int lane_e = d & 127;
    int chunk = blk >> 1, ntp = blk & 1;
    int lane = lane_e >> 2, e = lane_e & 3;
    int lq = lane >> 2, q4 = lane & 3;
    int nt = ntp*2 + (e >> 1);
    int pk_off = q4 + (e & 1)*4;
    int n = nt*8 + lq;
    int g = n >> 3, j = n & 7;
    const float* src = W + ((size_t)(g*HID + cb*8 + j))*HID + (chunk*8 + pk_off)*2;
    g_wt[(size_t)which*NCTA*WTILE + gi] = packh2(src[0], src[1]);
}

// per-warp GEMM pass over K=512 (proven R9): whalf = batch half, wkq = K half.
#define MMA_PASS(ABASE, W4) do {                                               \
    const uint4* ap0 = (ABASE) + whalf*2*2048 + wkq*1024 + lane;               \
    const uint4* ap1 = ap0 + 2048;                                             \
    uint4 afr[8][2];                                                           \
    _Pragma("unroll")                                                          \
    for (int s = 0; s < 8; s++) {                                              \
        afr[s][0] = __ldcg(ap0 + s*32);                                        \
        afr[s][1] = __ldcg(ap1 + s*32);                                        \
    }                                                                          \
    _Pragma("unroll")                                                          \
    for (int g8 = 0; g8 < 4; g8++) {                                           \
        _Pragma("unroll")                                                      \
        for (int s = 0; s < 8; s++) {                                          \
            const int cq = g8*8 + s;                                           \
            uint4 A0 = afr[s][0], A1 = afr[s][1];                              \
            if (g8 < 3) {                                                      \
                afr[s][0] = __ldcg(ap0 + (cq+8)*32);                           \
                afr[s][1] = __ldcg(ap1 + (cq+8)*32);                           \
            }                                                                  \
            const int bidx = (wkq*32 + cq)*64 + lane;                          \
            uint4 b01 = (W4)[bidx];                                            \
            uint4 b23 = (W4)[bidx + 32];                                       \
            uint32_t af0[4] = {A0.x, A0.y, A0.z, A0.w};                        \
            uint32_t af1[4] = {A1.x, A1.y, A1.z, A1.w};                        \
            uint32_t bf0[2] = {b01.x, b01.y};                                  \
            uint32_t bf1[2] = {b01.z, b01.w};                                  \
            uint32_t bf2[2] = {b23.x, b23.y};                                  \
            uint32_t bf3[2] = {b23.z, b23.w};                                  \
            mma16h(acc[0][0], af0, bf0); mma16h(acc[1][0], af1, bf0);          \
            mma16h(acc[0][1], af0, bf1); mma16h(acc[1][1], af1, bf1);          \
            mma16h(acc[0][2], af0, bf2); mma16h(acc[1][2], af1, bf2);          \
            mma16h(acc[0][3], af0, bf3); mma16h(acc[1][3], af1, bf3);          \
        }                                                                      \
    }                                                                          \
} while (0)

// store a warp's 4 split-K partial tiles into gate region rg (proven pattern)
#define STORE_GATES(RG) do {                                                   \
    float* gp = gsm + (RG)*GSZ;                                                \
    const int lq = lane >> 2, q4 = lane & 3;                                   \
    _Pragma("unroll")                                                          \
    for (int mt = 0; mt < 2; mt++) {                                           \
        const int r0 = whalf*32 + mt*16 + lq;                                  \
        _Pragma("unroll")                                                      \
        for (int nt = 0; nt < 4; nt++) {                                       \
            const int c = nt*8 + q4*2;                                         \
            gp[r0*GST + c]       = acc[mt][nt][0];                             \
            gp[r0*GST + c + 1]   = acc[mt][nt][1];                             \
            gp[(r0+8)*GST + c]   = acc[mt][nt][2];                             \
            gp[(r0+8)*GST + c+1] = acc[mt][nt][3];                             \
        }                                                                      \
    }                                                                          \
} while (0)

// ---- fused persistent LSTM, warp-specialized + x one step AHEAD ----
// warps 0-3: x-GEMM for step t+1 (no barrier dependence, double-buffered regions)
// warps 4-7: h-GEMM for step t (waits grid barrier)
__global__ void __launch_bounds__(256, 1) k_rnn(const float* __restrict__ c0,
                                                const float* __restrict__ mh,
                                                const float* __restrict__ b_ih,
                                                const float* __restrict__ b_hh,
                                                float* __restrict__ out) {
    extern __shared__ uint32_t sm[];
    uint32_t* sWh = sm;                    // W_hh tile, 16384 words
    uint32_t* sWi = sm + WTILE;            // W_ih tile, 16384 words
    float*    gsm = (float*)(sm + 2*WTILE);// 6 regions: x par0 (0,1), x par1 (2,3), h (4,5)

    const int cb   = blockIdx.x;
    const int tid  = threadIdx.x;
    const int lane = tid & 31;
    const int w    = tid >> 5;
    const bool isx = (w < 4);              // x-GEMM warps
    const int wl   = w & 3;
    const int whalf = wl & 1;              // batch half (32 rows)
    const int wkq   = wl >> 1;             // K half (512 k)

    // preload both W tiles (proven copy pattern)
    {
        const uint4* s0 = reinterpret_cast<const uint4*>(g_wt + (size_t)cb*WTILE);
        const uint4* s1 = reinterpret_cast<const uint4*>(g_wt + (size_t)(NCTA + cb)*WTILE);
        uint4* d0 = reinterpret_cast<uint4*>(sWh);
        uint4* d1 = reinterpret_cast<uint4*>(sWi);
        #pragma unroll
        for (int i = 0; i < 16; i++) d0[tid + i*256] = __ldcg(s0 + tid + i*256);
        #pragma unroll
        for (int i = 0; i < 16; i++) d1[tid + i*256] = __ldcg(s1 + tid + i*256);
    }

    // cell mapping: thread -> (batch pb, unit-pair p); units u0, u0+1
    const int pb = tid >> 2;
    const int p  = tid & 3;
    const int u0 = cb*8 + 2*p;
    const int gbase = pb*HID + u0;

    float2 c_r = *reinterpret_cast<const float2*>(c0 + gbase);
    float2 mh2 = *reinterpret_cast<const float2*>(mh + gbase);
    const int hwaddr = hp_addr(pb, cb*4 + p);

    float bs[2][4];
    #pragma unroll
    for (int i = 0; i < 2; i++)
        #pragma unroll
        for (int g = 0; g < 4; g++)
            bs[i][g] = b_ih[g*HID + u0 + i] + b_hh[g*HID + u0 + i];
    __syncthreads();   // W tiles resident

    const uint4* wh4 = reinterpret_cast<const uint4*>(sWh);
    const uint4* wi4 = reinterpret_cast<const uint4*>(sWi);

    // ---- pre-loop: x-warps compute xg[0] into x parity-0 regions (0,1) ----
    if (isx) {
        float acc[2][4][4];
        #pragma unroll
        for (int mt = 0; mt < 2; mt++)
            #pragma unroll
            for (int nt = 0; nt < 4; nt++)
                #pragma unroll
                for (int e = 0; e < 4; e++) acc[mt][nt][e] = 0.f;
        const uint4* xb = reinterpret_cast<const uint4*>(g_xv);
        MMA_PASS(xb, wi4);
        STORE_GATES(wkq);                  // regions 0,1
    }

    for (int t = 0; t < SEQ; ++t) {
        float acc[2][4][4];
        #pragma unroll
        for (int mt = 0; mt < 2; mt++)
            #pragma unroll
            for (int nt = 0; nt < 4; nt++)
                #pragma unroll
                for (int e = 0; e < 4; e++) acc[mt][nt][e] = 0.f;

        if (isx) {
            // compute xg[t+1] into x parity-((t+1)&1) regions
            if (t + 1 < SEQ) {
                const uint4* xb = reinterpret_cast<const uint4*>(g_xv + (size_t)(t+1)*32768);
                MMA_PASS(xb, wi4);
                STORE_GATES(((t+1) & 1)*2 + wkq);
            }
        } else {
            // h contribution for step t: wait for h[t] first (per-warp poll, proven)
            if (t > 0) {
                if (lane == 0) {
                    while (bar_ld_acquire(&g_bar[t-1]) < NCTA) { }
                }
                __syncwarp();
            }
            const uint4* hb = reinterpret_cast<const uint4*>(g_hm[t & 1]);
            MMA_PASS(hb, wh4);
            STORE_GATES(4 + wkq);          // regions 4,5
        }
        __syncthreads();

        // fused LSTM cell: x partials from parity (t&1) regions + h partials
        const float* gx = gsm + ((t & 1)*2)*GSZ;
        uint32_t* hmn = g_hm[(t + 1) & 1];
        float hnv[2], cnv[2];
        #pragma unroll
        for (int i = 0; i < 2; i++) {
            const int j = 2*p + i;
            float gt[4];
            #pragma unroll
            for (int g = 0; g < 4; g++) {
                const int c = g*8 + j;
                gt[g] = gx[pb*GST + c] + gx[GSZ + pb*GST + c]
                      + gsm[4*GSZ + pb*GST + c] + gsm[5*GSZ + pb*GST + c]
                      + bs[i][g];
            }
            float ig = sigf(gt[0]);
            float fg = sigf(gt[1]);
            float gv = tanh_f(gt[2]);
            float og = sigf(gt[3]);
            float cp = (i == 0) ? c_r.x : c_r.y;
            float cn = fg*cp + ig*gv;
            cnv[i] = cn;
            hnv[i] = og*tanh_f(cn);
        }
        c_r.x = cnv[0]; c_r.y = cnv[1];

        // publish h[t+1] FIRST, release, then private gmem work in the shadow
        hmn[hwaddr] = packh2(hnv[0]*mh2.x, hnv[1]*mh2.y);
        if (t < SEQ - 1) {
            __syncthreads();                            // all hmn writes + cell reads done
            if (tid == 0) bar_red_release(&g_bar[t]);   // arrive (release)
        }

        *reinterpret_cast<float2*>(out + (size_t)t*(NB*HID) + gbase)
            = make_float2(hnv[0], hnv[1]);
        if (t == SEQ - 1) {
            *reinterpret_cast<float2*>(out + SBH + gbase)          = make_float2(hnv[0], hnv[1]);
            *reinterpret_cast<float2*>(out + SBH + NB*HID + gbase) = make_float2(cnv[0], cnv[1]);
        }
    }
}

extern "C" void kernel_launch(void* const* d_in, const int* in_sizes, int n_in,
                              void* d_out, int out_size) {
    const float* x      = (const float*)d_in[0];
    const float* h0     = (const float*)d_in[1];
    const float* c0     = (const float*)d_in[2];
    const float* mask_x = (const float*)d_in[3];
    const float* mask_h = (const float*)d_in[4];
    const float* W_ih   = (const float*)d_in[5];
    const float* W_hh   = (const float*)d_in[6];
    const float* b_ih   = (const float*)d_in[7];
    const float* b_hh   = (const float*)d_in[8];
    float* out = (float*)d_out;

    const int smem_rnn = (2*WTILE + 6*GSZ) * 4;   // 131072 + 50688 = 181,760 B
    cudaFuncSetAttribute(k_rnn, cudaFuncAttributeMaxDynamicSharedMemorySize, smem_rnn);

    k_xprep<<<(SEQ*NB*HID/2)/256, 256>>>(x, mask_x);
    k_setup<<<(NB*HID/2)/256, 256>>>(h0, mask_h);
    k_wprep<<<(NCTA*WTILE)/256, 256>>>(W_hh, 0);
    k_wprep<<<(NCTA*WTILE)/256, 256>>>(W_ih, 1);
    k_rnn<<<NCTA, 256, smem_rnn>>>(c0, mask_h, b_ih, b_hh, out);
    (void)in_sizes; (void)n_in; (void)out_size;
}

// round 13
// speedup vs baseline: 1.3589x; 1.0001x over previous
#include <cuda_runtime.h>
#include <cuda_fp16.h>
#include <cstdint>

#define SEQ   256
#define NB    64
#define INP   1024
#define HID   1024
#define SBH   (SEQ*NB*HID)
#define NCTA  128
#define GST   33          // gsm row stride (floats)
#define GSZ   (64*GST)    // per-region gate area
#define WTILE 16384       // words per W tile per CTA (32 rows x 1024 k, fp16x2)

// ---- device scratch ----
__device__ uint32_t g_xv[(size_t)SEQ*NB*HID/2];  // x*mask_x, fp16x2, A-frag layout per step
__device__ uint32_t g_hm[2][NB*HID/2];           // masked h, fp16x2, A-frag layout
__device__ uint32_t g_wt[(size_t)2*NCTA*WTILE];  // [0]=W_hh tiles, [1]=W_ih tiles (B-frag)
__device__ int      g_bar[SEQ];                  // grid barrier counters

__device__ __forceinline__ void mma16h(float* d, const uint32_t* a, const uint32_t* b) {
    asm volatile(
        "mma.sync.aligned.m16n8k16.row.col.f32.f16.f16.f32 "
        "{%0,%1,%2,%3},{%4,%5,%6,%7},{%8,%9},{%0,%1,%2,%3};\n"
        : "+f"(d[0]), "+f"(d[1]), "+f"(d[2]), "+f"(d[3])
        : "r"(a[0]), "r"(a[1]), "r"(a[2]), "r"(a[3]), "r"(b[0]), "r"(b[1]));
}
__device__ __forceinline__ float sigf(float x)  { return 1.f/(1.f+__expf(-x)); }
__device__ __forceinline__ float tanh_f(float x){ return 2.f/(1.f+__expf(-2.f*x)) - 1.f; }
__device__ __forceinline__ void bar_red_release(int* p) {
    asm volatile("red.release.gpu.global.add.s32 [%0], 1;" :: "l"(p) : "memory");
}
__device__ __forceinline__ int bar_ld_acquire(int* p) {
    int v;
    asm volatile("ld.acquire.gpu.global.b32 %0, [%1];" : "=r"(v) : "l"(p) : "memory");
    return v;
}
__device__ __forceinline__ uint32_t packh2(float lo, float hi) {
    __half2 h = __floats2half2_rn(lo, hi);   // lo -> low 16 bits (even k)
    return *reinterpret_cast<uint32_t*>(&h);
}
// fp16 A-frag layout: word address for (batch b, k-pair pk); pk = k/2  (proven)
__device__ __forceinline__ int hp_addr(int b, int pk) {
    int mt = b >> 4, rb = b & 15;
    int c  = pk >> 3, pkl = pk & 7;
    int lane = (rb & 7)*4 + (pkl & 3);
    int e    = (pkl >> 2)*2 + (rb >> 3);
    return (mt*64 + c)*128 + lane*4 + e;
}

// ---- x*mask_x -> fp16x2 A-frag layout, per step (proven) ----
__global__ void k_xprep(const float* __restrict__ x, const float* __restrict__ mx) {
    int i = blockIdx.x*256 + threadIdx.x;
    int t = i >> 15;
    int d = i & 32767;
    int b = d >> 9, pk = d & 511;
    int u0 = pk*2;
    const float* xs = x  + ((size_t)t*NB + b)*INP + u0;
    const float* ms = mx + (size_t)b*INP + u0;
    g_xv[(size_t)t*32768 + hp_addr(b, pk)] = packh2(xs[0]*ms[0], xs[1]*ms[1]);
}

// ---- init: hm0 = fp16x2(h0*mask_h) in frag layout; zero barriers (proven) ----
__global__ void k_setup(const float* __restrict__ h0, const float* __restrict__ mh) {
    int i = blockIdx.x*256 + threadIdx.x;
    int b = i >> 9, pk = i & 511;
    int u0 = pk*2;
    int s = b*HID + u0;
    g_hm[0][hp_addr(b, pk)] = packh2(h0[s]*mh[s], h0[s+1]*mh[s+1]);
    if (blockIdx.x == 0) g_bar[threadIdx.x] = 0;
}

// ---- W prep: per-CTA fp16x2 tiles in B-fragment layout (proven) ----
__global__ void k_wprep(const float* __restrict__ W, int which) {
    int gi = blockIdx.x*256 + threadIdx.x;
    int cb = gi >> 14;
    int d  = gi & 16383;
    int blk = d >> 7;
    int lane_e = d & 127;
    int chunk = blk >> 1, ntp = blk & 1;
    int lane = lane_e >> 2, e = lane_e & 3;
    int lq = lane >> 2, q4 = lane & 3;
    int nt = ntp*2 + (e >> 1);
    int pk_off = q4 + (e & 1)*4;
    int n = nt*8 + lq;
    int g = n >> 3, j = n & 7;
    const float* src = W + ((size_t)(g*HID + cb*8 + j))*HID + (chunk*8 + pk_off)*2;
    g_wt[(size_t)which*NCTA*WTILE + gi] = packh2(src[0], src[1]);
}

// per-warp GEMM pass over K=512 (proven R9): whalf = batch half, wkq = K half.
#define MMA_PASS(ABASE, W4) do {                                               \
    const uint4* ap0 = (ABASE) + whalf*2*2048 + wkq*1024 + lane;               \
    const uint4* ap1 = ap0 + 2048;                                             \
    uint4 afr[8][2];                                                           \
    _Pragma("unroll")                                                          \
    for (int s = 0; s < 8; s++) {                                              \
        afr[s][0] = __ldcg(ap0 + s*32);                                        \
        afr[s][1] = __ldcg(ap1 + s*32);                                        \
    }                                                                          \
    _Pragma("unroll")                                                          \
    for (int g8 = 0; g8 < 4; g8++) {                                           \
        _Pragma("unroll")                                                      \
        for (int s = 0; s < 8; s++) {                                          \
            const int cq = g8*8 + s;                                           \
            uint4 A0 = afr[s][0], A1 = afr[s][1];                              \
            if (g8 < 3) {                                                      \
                afr[s][0] = __ldcg(ap0 + (cq+8)*32);                           \
                afr[s][1] = __ldcg(ap1 + (cq+8)*32);                           \
            }                                                                  \
            const int bidx = (wkq*32 + cq)*64 + lane;                          \
            uint4 b01 = (W4)[bidx];                                            \
            uint4 b23 = (W4)[bidx + 32];                                       \
            uint32_t af0[4] = {A0.x, A0.y, A0.z, A0.w};                        \
            uint32_t af1[4] = {A1.x, A1.y, A1.z, A1.w};                        \
            uint32_t bf0[2] = {b01.x, b01.y};                                  \
            uint32_t bf1[2] = {b01.z, b01.w};                                  \
            uint32_t bf2[2] = {b23.x, b23.y};                                  \
            uint32_t bf3[2] = {b23.z, b23.w};                                  \
            mma16h(acc[0][0], af0, bf0); mma16h(acc[1][0], af1, bf0);          \
            mma16h(acc[0][1], af0, bf1); mma16h(acc[1][1], af1, bf1);          \
            mma16h(acc[0][2], af0, bf2); mma16h(acc[1][2], af1, bf2);          \
            mma16h(acc[0][3], af0, bf3); mma16h(acc[1][3], af1, bf3);          \
        }                                                                      \
    }                                                                          \
} while (0)

// store a warp's 4 split-K partial tiles into gate region rg (proven pattern)
#define STORE_GATES(RG) do {                                                   \
    float* gp = gsm + (RG)*GSZ;                                                \
    const int lq = lane >> 2, q4 = lane & 3;                                   \
    _Pragma("unroll")                                                          \
    for (int mt = 0; mt < 2; mt++) {                                           \
        const int r0 = whalf*32 + mt*16 + lq;                                  \
        _Pragma("unroll")                                                      \
        for (int nt = 0; nt < 4; nt++) {                                       \
            const int c = nt*8 + q4*2;                                         \
            gp[r0*GST + c]       = acc[mt][nt][0];                             \
            gp[r0*GST + c + 1]   = acc[mt][nt][1];                             \
            gp[(r0+8)*GST + c]   = acc[mt][nt][2];                             \
            gp[(r0+8)*GST + c+1] = acc[mt][nt][3];                             \
        }                                                                      \
    }                                                                          \
} while (0)

// ---- fused persistent LSTM, warp-specialized + x one step AHEAD ----
// warps 0-3: x-GEMM for step t+1 (no barrier dependence, double-buffered regions)
// warps 4-7: h-GEMM for step t (waits grid barrier)
__global__ void __launch_bounds__(256, 1) k_rnn(const float* __restrict__ c0,
                                                const float* __restrict__ mh,
                                                const float* __restrict__ b_ih,
                                                const float* __restrict__ b_hh,
                                                float* __restrict__ out) {
    extern __shared__ uint32_t sm[];
    uint32_t* sWh = sm;                    // W_hh tile, 16384 words
    uint32_t* sWi = sm + WTILE;            // W_ih tile, 16384 words
    float*    gsm = (float*)(sm + 2*WTILE);// 6 regions: x par0 (0,1), x par1 (2,3), h (4,5)

    const int cb   = blockIdx.x;
    const int tid  = threadIdx.x;
    const int lane = tid & 31;
    const int w    = tid >> 5;
    const bool isx = (w < 4);              // x-GEMM warps
    const int wl   = w & 3;
    const int whalf = wl & 1;              // batch half (32 rows)
    const int wkq   = wl >> 1;             // K half (512 k)

    // preload both W tiles (proven copy pattern)
    {
        const uint4* s0 = reinterpret_cast<const uint4*>(g_wt + (size_t)cb*WTILE);
        const uint4* s1 = reinterpret_cast<const uint4*>(g_wt + (size_t)(NCTA + cb)*WTILE);
        uint4* d0 = reinterpret_cast<uint4*>(sWh);
        uint4* d1 = reinterpret_cast<uint4*>(sWi);
        #pragma unroll
        for (int i = 0; i < 16; i++) d0[tid + i*256] = __ldcg(s0 + tid + i*256);
        #pragma unroll
        for (int i = 0; i < 16; i++) d1[tid + i*256] = __ldcg(s1 + tid + i*256);
    }

    // cell mapping: thread -> (batch pb, unit-pair p); units u0, u0+1
    const int pb = tid >> 2;
    const int p  = tid & 3;
    const int u0 = cb*8 + 2*p;
    const int gbase = pb*HID + u0;

    float2 c_r = *reinterpret_cast<const float2*>(c0 + gbase);
    float2 mh2 = *reinterpret_cast<const float2*>(mh + gbase);
    const int hwaddr = hp_addr(pb, cb*4 + p);

    float bs[2][4];
    #pragma unroll
    for (int i = 0; i < 2; i++)
        #pragma unroll
        for (int g = 0; g < 4; g++)
            bs[i][g] = b_ih[g*HID + u0 + i] + b_hh[g*HID + u0 + i];
    __syncthreads();   // W tiles resident

    const uint4* wh4 = reinterpret_cast<const uint4*>(sWh);
    const uint4* wi4 = reinterpret_cast<const uint4*>(sWi);

    // ---- pre-loop: x-warps compute xg[0] into x parity-0 regions (0,1) ----
    if (isx) {
        float acc[2][4][4];
        #pragma unroll
        for (int mt = 0; mt < 2; mt++)
            #pragma unroll
            for (int nt = 0; nt < 4; nt++)
                #pragma unroll
                for (int e = 0; e < 4; e++) acc[mt][nt][e] = 0.f;
        const uint4* xb = reinterpret_cast<const uint4*>(g_xv);
        MMA_PASS(xb, wi4);
        STORE_GATES(wkq);                  // regions 0,1
    }

    for (int t = 0; t < SEQ; ++t) {
        float acc[2][4][4];
        #pragma unroll
        for (int mt = 0; mt < 2; mt++)
            #pragma unroll
            for (int nt = 0; nt < 4; nt++)
                #pragma unroll
                for (int e = 0; e < 4; e++) acc[mt][nt][e] = 0.f;

        if (isx) {
            // compute xg[t+1] into x parity-((t+1)&1) regions
            if (t + 1 < SEQ) {
                const uint4* xb = reinterpret_cast<const uint4*>(g_xv + (size_t)(t+1)*32768);
                MMA_PASS(xb, wi4);
                STORE_GATES(((t+1) & 1)*2 + wkq);
            }
        } else {
            // h contribution for step t: wait for h[t] first (per-warp poll, proven)
            if (t > 0) {
                if (lane == 0) {
                    while (bar_ld_acquire(&g_bar[t-1]) < NCTA) { }
                }
                __syncwarp();
            }
            const uint4* hb = reinterpret_cast<const uint4*>(g_hm[t & 1]);
            MMA_PASS(hb, wh4);
            STORE_GATES(4 + wkq);          // regions 4,5
        }
        __syncthreads();

        // fused LSTM cell: x partials from parity (t&1) regions + h partials
        const float* gx = gsm + ((t & 1)*2)*GSZ;
        uint32_t* hmn = g_hm[(t + 1) & 1];
        float hnv[2], cnv[2];
        #pragma unroll
        for (int i = 0; i < 2; i++) {
            const int j = 2*p + i;
            float gt[4];
            #pragma unroll
            for (int g = 0; g < 4; g++) {
                const int c = g*8 + j;
                gt[g] = gx[pb*GST + c] + gx[GSZ + pb*GST + c]
                      + gsm[4*GSZ + pb*GST + c] + gsm[5*GSZ + pb*GST + c]
                      + bs[i][g];
            }
            float ig = sigf(gt[0]);
            float fg = sigf(gt[1]);
            float gv = tanh_f(gt[2]);
            float og = sigf(gt[3]);
            float cp = (i == 0) ? c_r.x : c_r.y;
            float cn = fg*cp + ig*gv;
            cnv[i] = cn;
            hnv[i] = og*tanh_f(cn);
        }
        c_r.x = cnv[0]; c_r.y = cnv[1];

        // publish h[t+1] FIRST, release, then private gmem work in the shadow
        hmn[hwaddr] = packh2(hnv[0]*mh2.x, hnv[1]*mh2.y);
        if (t < SEQ - 1) {
            __syncthreads();                            // all hmn writes + cell reads done
            if (tid == 0) bar_red_release(&g_bar[t]);   // arrive (release)
        }

        *reinterpret_cast<float2*>(out + (size_t)t*(NB*HID) + gbase)
            = make_float2(hnv[0], hnv[1]);
        if (t == SEQ - 1) {
            *reinterpret_cast<float2*>(out + SBH + gbase)          = make_float2(hnv[0], hnv[1]);
            *reinterpret_cast<float2*>(out + SBH + NB*HID + gbase) = make_float2(cnv[0], cnv[1]);
        }
    }
}

extern "C" void kernel_launch(void* const* d_in, const int* in_sizes, int n_in,
                              void* d_out, int out_size) {
    const float* x      = (const float*)d_in[0];
    const float* h0     = (const float*)d_in[1];
    const float* c0     = (const float*)d_in[2];
    const float* mask_x = (const float*)d_in[3];
    const float* mask_h = (const float*)d_in[4];
    const float* W_ih   = (const float*)d_in[5];
    const float* W_hh   = (const float*)d_in[6];
    const float* b_ih   = (const float*)d_in[7];
    const float* b_hh   = (const float*)d_in[8];
    float* out = (float*)d_out;

    const int smem_rnn = (2*WTILE + 6*GSZ) * 4;   // 131072 + 50688 = 181,760 B
    cudaFuncSetAttribute(k_rnn, cudaFuncAttributeMaxDynamicSharedMemorySize, smem_rnn);

    k_xprep<<<(SEQ*NB*HID/2)/256, 256>>>(x, mask_x);
    k_setup<<<(NB*HID/2)/256, 256>>>(h0, mask_h);
    k_wprep<<<(NCTA*WTILE)/256, 256>>>(W_hh, 0);
    k_wprep<<<(NCTA*WTILE)/256, 256>>>(W_ih, 1);
    k_rnn<<<NCTA, 256, smem_rnn>>>(c0, mask_h, b_ih, b_hh, out);
    (void)in_sizes; (void)n_in; (void)out_size;
}